// round 15
// baseline (speedup 1.0000x reference)
#include <cuda_runtime.h>
#include <cuda_bf16.h>
#include <cstdint>

#define BATCH   16
#define NPRED   25200
#define NC      80
#define STRIDE  85
#define TOPK    4096
#define MAXDET  1000
#define NWORDS  64            // TOPK/64
#define NITEMS  25            // ceil(NPRED/1024)
#define ECAP    8192          // per-batch suppression-pair capacity (fast path)
#define MCACHE  1024          // k_mask shared box-cache capacity
#define CONF_THRES 0.25f
#define IOU_THRES  0.45f
#define MAX_WH     7680.0f

#define U_BASE    0xBE800000u   // order-key of conf==0.25 (exclusive lower bound)
#define U_INVALID 0x407FFFFFu   // order-key of s==-1.0

typedef unsigned long long ull;

// ---------------- scratch (no allocation allowed; __device__ globals) ----------------
__device__ unsigned  g_u[BATCH * NPRED];        // order key (score fully recoverable)
__device__ int       g_cls[BATCH * NPRED];      // argmax class
__device__ float     g_selScore[BATCH * TOPK];
__device__ int       g_selCls[BATCH * TOPK];
__device__ float     g_box[BATCH * TOPK * 4];   // xyxy (no offset)
__device__ float     g_ob[BATCH * TOPK * 4];    // offset boxes
__device__ float     g_area[BATCH * TOPK];      // area of offset box
__device__ int       g_nvalid[BATCH];
__device__ int       g_clsCnt[BATCH * NC];      // per-class member counts
__device__ int       g_clsList[BATCH * NC * TOPK / 64 * 64]; // capacity TOPK per class
__device__ int       g_ecnt[BATCH];             // suppression pair counts
__device__ unsigned  g_epair[BATCH * ECAP];     // packed (i<<12)|j, i<j
__device__ int       g_done[BATCH];             // per-batch mask-block completion count

// -------- kernel 1: conf / argmax / order-key (REDUX max + ballot argmax) ------------
// 12 rows * 85 floats = 1020 floats = 255 float4, and group base is 16B-aligned.
// Products obj*cls are >= 0, so their float bits compare as unsigned: the block
// max is one REDUX.MAX; the exact first-index argmax is recovered by equality
// ballots over the identical fl(obj*cls_c) values the reference computes.
__global__ void __launch_bounds__(384) k_prep(const float4* __restrict__ pred4) {
    __shared__ float4 buf4[255];
    int grp = blockIdx.x;
    int t = threadIdx.x;
    if (t < 255) buf4[t] = pred4[grp * 255 + t];
    __syncthreads();
    const float* buf = (const float*)buf4;
    int w = t >> 5, lane = t & 31;          // 12 warps, one row each
    const float* r = buf + w * 85;
    float obj = r[4];
    float p0 = __fmul_rn(obj, r[5 + lane]);          // classes 0..31
    float p1 = __fmul_rn(obj, r[37 + lane]);         // classes 32..63
    float p2 = (lane < 16) ? __fmul_rn(obj, r[69 + lane]) : 0.0f;  // classes 64..79
    unsigned b0 = __float_as_uint(p0);
    unsigned b1 = __float_as_uint(p1);
    unsigned b2 = __float_as_uint(p2);
    unsigned m = max(b0, max(b1, b2));
    unsigned best = __reduce_max_sync(0xFFFFFFFFu, m);   // single REDUX.MAX
    unsigned e0 = __ballot_sync(0xFFFFFFFFu, b0 == best);
    unsigned e1 = __ballot_sync(0xFFFFFFFFu, b1 == best);
    unsigned e2 = __ballot_sync(0xFFFFFFFFu, b2 == best) & 0xFFFFu;  // mask padding
    if (lane == 0) {
        int bi = e0 ? (__ffs(e0) - 1) : (e1 ? (32 + __ffs(e1) - 1) : (64 + __ffs(e2) - 1));
        float s = __uint_as_float(best);
        s = (s > CONF_THRES) ? s : -1.0f;
        unsigned ub = __float_as_uint(s);
        unsigned uo = (ub & 0x80000000u) ? ~ub : (ub | 0x80000000u); // ascending order map
        int row = grp * 12 + w;
        g_u[row] = uo; g_cls[row] = bi;
    }
}

// ---------------- kernel 2: top-4096 (histogram threshold + bucket rank) -------------
__device__ __forceinline__ ull shfl_xor_u64(ull x, int m) {
    unsigned lo = __shfl_xor_sync(0xFFFFFFFFu, (unsigned)x, m);
    unsigned hi = __shfl_xor_sync(0xFFFFFFFFu, (unsigned)(x >> 32), m);
    return ((ull)hi << 32) | lo;
}

// inclusive suffix scan over 1024 threads (3 barriers, shfl-based)
__device__ __forceinline__ int blockSuffixScan1024(int v, int tid, int* warpBuf) {
    int lane = tid & 31, w = tid >> 5;
    __syncthreads();     // protect warpBuf from previous use
    #pragma unroll
    for (int off = 1; off < 32; off <<= 1) {
        int t = __shfl_down_sync(0xFFFFFFFFu, v, off);
        if (lane + off < 32) v += t;
    }
    if (lane == 0) warpBuf[w] = v;   // whole-warp sum
    __syncthreads();
    if (w == 0) {
        int s = warpBuf[lane];
        #pragma unroll
        for (int off = 1; off < 32; off <<= 1) {
            int t = __shfl_down_sync(0xFFFFFFFFu, s, off);
            if (lane + off < 32) s += t;
        }
        warpBuf[lane] = s;           // inclusive suffix over warp sums
    }
    __syncthreads();
    int later = (w < 31) ? warpBuf[w + 1] : 0;
    return v + later;
}

#define NIT_U   16
#define NIT_I   15
#define CNT_TOTAL 64
// dynamic smem layout: keys[4096] ull (32KB) | selC[4096] int (16KB) |
//                      fill[4096] int (16KB) | grpSuf[1024] int (4KB)  = 69632 B
#define SELECT_SMEM 69632

extern __shared__ char dynsmem[];

__global__ void __launch_bounds__(1024) k_select(const float* __restrict__ pred) {
    int b = blockIdx.x;
    int tid = threadIdx.x;
    int lane = tid & 31;
    const unsigned* u = g_u + b * NPRED;
    ull* keys   = (ull*)dynsmem;                 // 4096 keys
    int* selC   = (int*)(dynsmem + 32768);       // hist -> selected counts
    int* fill   = (int*)(dynsmem + 49152);       // bucket fill counters
    int* grpSuf = (int*)(dynsmem + 65536);       // 1024 group suffix sums
    __shared__ int cnts[CNT_TOTAL];
    __shared__ int warpBuf[32];
    __shared__ int sB, sNeed, sBinCnt, sMode, sG, sMax;
    __shared__ ull sKstar;
    __shared__ int scnt, svalid;

    // zero per-batch side state
    if (tid < NC) g_clsCnt[b * NC + tid] = 0;
    if (tid == 0) { g_ecnt[b] = 0; g_done[b] = 0; scnt = 0; svalid = 0; sMax = 0; }
    if (tid < CNT_TOTAL) cnts[tid] = 0;

    // ---- load all keys into registers (one pass over memory) ----
    unsigned uv[NITEMS];
    #pragma unroll
    for (int k = 0; k < NITEMS; ++k) {
        int i = k * 1024 + tid;
        uv[k] = (i < NPRED) ? u[i] : 0u;   // padding u=0: never matches anything
    }

    // ---- phase 1: 4096-bin histogram of valid keys ----
    #pragma unroll
    for (int h = tid; h < 4096; h += 1024) selC[h] = 0;
    __syncthreads();
    #pragma unroll
    for (int k = 0; k < NITEMS; ++k) {
        unsigned k0 = uv[k];
        if (k0 > U_BASE) {
            int bin = (int)((k0 - U_BASE - 1u) >> 12);
            if (bin > 4095) bin = 4095;
            atomicAdd(&selC[bin], 1);
        }
    }
    __syncthreads();

    // ---- phase 2: suffix-scan over 1024 groups of 4 bins (shfl-based) ----
    {
        int g4 = tid * 4;
        int v = selC[g4] + selC[g4 + 1] + selC[g4 + 2] + selC[g4 + 3];
        int r = blockSuffixScan1024(v, tid, warpBuf);
        grpSuf[tid] = r;
        __syncthreads();
    }
    int totalValid = grpSuf[0];
    if (totalValid >= TOPK) {
        if (grpSuf[tid] >= TOPK && (tid == 1023 || grpSuf[tid + 1] < TOPK)) sG = tid;
        __syncthreads();
        if (tid == 0) {
            int g = sG;
            int c2 = (g < 1023) ? grpSuf[g + 1] : 0;
            int Bst = g * 4, cntGt = c2;
            for (int bb = g * 4 + 3; bb >= g * 4; --bb) {
                if (c2 + selC[bb] >= TOPK) { Bst = bb; cntGt = c2; break; }
                c2 += selC[bb];
            }
            sB = Bst; sNeed = TOPK - cntGt; sBinCnt = selC[Bst]; sMode = 0;
        }
    } else {
        if (tid == 0) { sB = -1; sNeed = TOPK - totalValid; sBinCnt = NPRED - totalValid; sMode = 1; }
    }
    __syncthreads();
    int Bst = sB, need = sNeed, binCnt = sBinCnt, mode = sMode;
    __syncthreads();

    // ---- phase 3: exact threshold key K* ----
    if (binCnt <= TOPK) {
        // gather candidate-bin keys into keys[], tiny bitonic, K* = need-th largest
        if (tid == 0) scnt = 0;
        __syncthreads();
        #pragma unroll
        for (int k = 0; k < NITEMS; ++k) {
            int i = k * 1024 + tid;
            unsigned k0 = uv[k];
            bool m;
            if (mode == 0) {
                int bin = -1;
                if (k0 > U_BASE) {
                    bin = (int)((k0 - U_BASE - 1u) >> 12);
                    if (bin > 4095) bin = 4095;
                }
                m = (bin == Bst);
            } else {
                m = (k0 == U_INVALID) && (i < NPRED);
            }
            if (m) {
                int p = atomicAdd(&scnt, 1);
                if (p < TOPK) keys[p] = ((ull)k0 << 32) | (unsigned)(~i);
            }
        }
        __syncthreads();
        int cnt = scnt;
        int n = 2; while (n < cnt) n <<= 1;
        for (int e = tid; e < n; e += 1024) if (e >= cnt) keys[e] = 0ULL;
        __syncthreads();
        for (int k = 2; k <= n; k <<= 1) {
            for (int j = k >> 1; j >= 1; j >>= 1) {
                for (int x = tid; x < n; x += 1024) {
                    int l = x ^ j;
                    if (l > x) {
                        bool desc = ((x & k) == 0);
                        ull a = keys[x], c = keys[l];
                        if (desc ? (a < c) : (a > c)) { keys[x] = c; keys[l] = a; }
                    }
                }
                __syncthreads();
            }
        }
        if (tid == 0) sKstar = keys[need - 1];
        __syncthreads();
    } else {
        // fallback (never expected): 2-bit search + tie search
        unsigned U = 0u;
        #pragma unroll
        for (int it = 0; it < NIT_U; ++it) {
            int s = 30 - 2 * it;
            unsigned c1t = U + (1u << s);
            int c1 = 0, c2 = 0, c3 = 0;
            #pragma unroll
            for (int k = 0; k < NITEMS; ++k) {
                unsigned k0 = uv[k];
                if (k0 >= c1t) {
                    unsigned w = (k0 - U) >> s;
                    c1++;
                    if (w >= 2) c2++;
                    if (w >= 3) c3++;
                }
            }
            c1 = __reduce_add_sync(0xFFFFFFFFu, c1);
            c2 = __reduce_add_sync(0xFFFFFFFFu, c2);
            c3 = __reduce_add_sync(0xFFFFFFFFu, c3);
            if (lane == 0) {
                atomicAdd(&cnts[it * 3 + 0], c1);
                atomicAdd(&cnts[it * 3 + 1], c2);
                atomicAdd(&cnts[it * 3 + 2], c3);
            }
            __syncthreads();
            int t1 = cnts[it * 3 + 0], t2 = cnts[it * 3 + 1], t3 = cnts[it * 3 + 2];
            unsigned v = (t3 >= TOPK) ? 3u : (t2 >= TOPK) ? 2u : (t1 >= TOPK) ? 1u : 0u;
            U |= v << s;
        }
        unsigned ustar = U;
        {
            int c = 0;
            #pragma unroll
            for (int k = 0; k < NITEMS; ++k) c += (uv[k] > ustar);
            c = __reduce_add_sync(0xFFFFFFFFu, c);
            if (lane == 0) atomicAdd(&cnts[48], c);
            __syncthreads();
        }
        int need2 = TOPK - cnts[48];
        int M = 0;
        #pragma unroll
        for (int it = 0; it < NIT_I; ++it) {
            int bit = 14 - it;
            int candi = M | (1 << bit);
            int c = 0;
            #pragma unroll
            for (int k = 0; k < NITEMS; ++k) {
                int i = k * 1024 + tid;
                if (uv[k] == ustar && i < candi && i < NPRED) c++;
            }
            c = __reduce_add_sync(0xFFFFFFFFu, c);
            if (lane == 0) atomicAdd(&cnts[49 + it], c);
            __syncthreads();
            if (cnts[49 + it] < need2) M = candi;
        }
        if (tid == 0) sKstar = ((ull)ustar << 32) | (unsigned)(~M);
        __syncthreads();
    }
    ull Kstar = sKstar;
    __syncthreads();

    // ---- phase 4: selected-count conversion + bucket-size guard ----
    bool fastOK = false;
    if (mode == 0) {
        #pragma unroll
        for (int h = tid; h < 4096; h += 1024) {
            if (h < Bst) selC[h] = 0;
            else if (h == Bst) selC[h] = need;
        }
        __syncthreads();
        int mymax = 0;
        #pragma unroll
        for (int h = tid; h < 4096; h += 1024) if (selC[h] > mymax) mymax = selC[h];
        mymax = __reduce_max_sync(0xFFFFFFFFu, mymax);
        if (lane == 0) atomicMax(&sMax, mymax);
        __syncthreads();
        fastOK = (sMax <= 64);
    }

    if (fastOK) {
        // ---- phase 5a: suffix-scan of selected counts, scatter to final slots ----
        {
            int g4 = tid * 4;
            int v = selC[g4] + selC[g4 + 1] + selC[g4 + 2] + selC[g4 + 3];
            int r = blockSuffixScan1024(v, tid, warpBuf);
            grpSuf[tid] = r;
        }
        #pragma unroll
        for (int h = tid; h < 4096; h += 1024) fill[h] = 0;
        __syncthreads();
        #pragma unroll
        for (int k = 0; k < NITEMS; ++k) {
            int i = k * 1024 + tid;
            unsigned k0 = uv[k];
            ull key = ((ull)k0 << 32) | (unsigned)(~i);
            if (i < NPRED && key >= Kstar) {
                int bin = (int)((k0 - U_BASE - 1u) >> 12);
                if (bin > 4095) bin = 4095;
                int g = bin >> 2;
                int base = (g < 1023) ? grpSuf[g + 1] : 0;
                for (int b2 = (g << 2) + 3; b2 > bin; --b2) base += selC[b2];
                int slot = base + atomicAdd(&fill[bin], 1);
                keys[slot] = key;
            }
        }
        __syncthreads();
        // ---- per-bucket insertion sort (descending; buckets <= 64) ----
        for (int bin = tid; bin < 4096; bin += 1024) {
            int cnt = selC[bin];
            if (cnt > 1) {
                int g = bin >> 2;
                int base = (g < 1023) ? grpSuf[g + 1] : 0;
                for (int b2 = (g << 2) + 3; b2 > bin; --b2) base += selC[b2];
                for (int a = 1; a < cnt; ++a) {
                    ull kv = keys[base + a];
                    int q = a - 1;
                    while (q >= 0 && keys[base + q] < kv) { keys[base + q + 1] = keys[base + q]; --q; }
                    keys[base + q + 1] = kv;
                }
            }
        }
        __syncthreads();
    } else {
        // ---- phase 5b (fallback): gather + full hybrid bitonic ----
        if (tid == 0) scnt = 0;
        __syncthreads();
        #pragma unroll
        for (int k = 0; k < NITEMS; ++k) {
            int i = k * 1024 + tid;
            ull key = ((ull)uv[k] << 32) | (unsigned)(~i);
            bool m = (i < NPRED) && (key >= Kstar);
            unsigned act = __ballot_sync(0xFFFFFFFFu, m);
            if (m) {
                int leader = __ffs(act) - 1;
                int rank = __popc(act & ((1u << lane) - 1u));
                int base;
                if (lane == leader) base = atomicAdd(&scnt, __popc(act));
                base = __shfl_sync(act, base, leader);
                int pos = base + rank;
                if (pos < TOPK) keys[pos] = key;
            }
        }
        __syncthreads();
        ull v[4];
        #pragma unroll
        for (int e = 0; e < 4; ++e) v[e] = keys[tid * 4 + e];
        for (int k = 2; k <= TOPK; k <<= 1) {
            for (int j = k >> 1; j >= 1; j >>= 1) {
                if (j >= 128) {
                    #pragma unroll
                    for (int e = 0; e < 4; ++e) keys[tid * 4 + e] = v[e];
                    __syncthreads();
                    #pragma unroll
                    for (int e = 0; e < 4; ++e) {
                        int idx = tid * 4 + e;
                        ull pv = keys[idx ^ j];
                        bool d = ((idx & k) == 0);
                        bool lower = ((idx & j) == 0);
                        bool keepmax = (d == lower);
                        ull mx = (v[e] > pv) ? v[e] : pv;
                        ull mn = (v[e] > pv) ? pv : v[e];
                        v[e] = keepmax ? mx : mn;
                    }
                    __syncthreads();
                } else if (j >= 4) {
                    int dl = j >> 2;
                    #pragma unroll
                    for (int e = 0; e < 4; ++e) {
                        ull pv = shfl_xor_u64(v[e], dl);
                        int idx = tid * 4 + e;
                        bool d = ((idx & k) == 0);
                        bool lower = ((tid & dl) == 0);
                        bool keepmax = (d == lower);
                        ull mx = (v[e] > pv) ? v[e] : pv;
                        ull mn = (v[e] > pv) ? pv : v[e];
                        v[e] = keepmax ? mx : mn;
                    }
                } else {
                    #pragma unroll
                    for (int e = 0; e < 4; ++e) {
                        if ((e & j) == 0) {
                            int idx = tid * 4 + e;
                            bool d = ((idx & k) == 0);
                            ull a = v[e], c2 = v[e + j];
                            if (d ? (a < c2) : (a > c2)) { v[e] = c2; v[e + j] = a; }
                        }
                    }
                }
            }
        }
        #pragma unroll
        for (int e = 0; e < 4; ++e) keys[tid * 4 + e] = v[e];
        __syncthreads();
    }

    // ---- emit + fused gather of boxes / classes / areas + class bucketing ----
    int lv = 0;
    #pragma unroll
    for (int e = 0; e < 4; ++e) {
        int rank = tid * 4 + e;
        ull key = keys[rank];
        unsigned k0 = (unsigned)(key >> 32);
        int i = (int)(~(unsigned)(key & 0xFFFFFFFFull));
        int gi = b * TOPK + rank;
        // s exactly recovered from the order key (mapping is invertible)
        float s = (k0 & 0x80000000u) ? __uint_as_float(k0 & 0x7FFFFFFFu) : -1.0f;
        g_selScore[gi] = s;
        lv += (s > 0.0f);
        int ci = g_cls[b * NPRED + i];
        g_selCls[gi] = ci;
        int slot = atomicAdd(&g_clsCnt[b * NC + ci], 1);
        g_clsList[(b * NC + ci) * TOPK + slot] = rank;
        const float* p = pred + ((size_t)b * NPRED + i) * STRIDE;
        float xc = p[0], yc = p[1], w = p[2], h = p[3];
        float hw = __fmul_rn(w, 0.5f), hh = __fmul_rn(h, 0.5f);
        float x1 = __fsub_rn(xc, hw), y1 = __fsub_rn(yc, hh);
        float x2 = __fadd_rn(xc, hw), y2 = __fadd_rn(yc, hh);
        float off = __fmul_rn((float)ci, MAX_WH);
        float ox1 = __fadd_rn(x1, off), oy1 = __fadd_rn(y1, off);
        float ox2 = __fadd_rn(x2, off), oy2 = __fadd_rn(y2, off);
        ((float4*)g_box)[gi] = make_float4(x1, y1, x2, y2);
        ((float4*)g_ob)[gi]  = make_float4(ox1, oy1, ox2, oy2);
        g_area[gi] = __fmul_rn(__fsub_rn(ox2, ox1), __fsub_rn(oy2, oy1));
    }
    lv = __reduce_add_sync(0xFFFFFFFFu, lv);
    if (lane == 0) atomicAdd(&svalid, lv);
    __syncthreads();
    if (tid == 0) g_nvalid[b] = svalid;
}

// -------- kernel 3: per-class IoU -> pairs, then LAST block per batch suppresses -----
__device__ __forceinline__ bool iou_exceeds(float ax1, float ay1, float ax2, float ay2,
                                            float aA,
                                            float bx1, float by1, float bx2, float by2,
                                            float aB) {
    float ltx = fmaxf(ax1, bx1);
    float lty = fmaxf(ay1, by1);
    float rbx = fminf(ax2, bx2);
    float rby = fminf(ay2, by2);
    float wv = fmaxf(__fsub_rn(rbx, ltx), 0.0f);
    float hv = fmaxf(__fsub_rn(rby, lty), 0.0f);
    float inter = __fmul_rn(wv, hv);
    if (inter <= 0.0f) return false;
    float denom = __fadd_rn(__fsub_rn(__fadd_rn(aA, aB), inter), 1e-7f);
    return __fdiv_rn(inter, denom) > IOU_THRES;
}

struct MaskShm {
    float sx1[MCACHE], sy1[MCACHE], sx2[MCACHE], sy2[MCACHE], sar[MCACHE];
    int   srk[MCACHE];
};
struct SupShm {
    unsigned sedge[ECAP];
    ull remA[NWORDS], remB[NWORDS], keepw[NWORDS];
    int prefix[NWORDS];
};

__global__ void __launch_bounds__(256) k_mask(float* __restrict__ out) {
    __shared__ union { MaskShm m; SupShm s; } shm;
    __shared__ int sLast, schanged;
    int c = blockIdx.x;     // class
    int b = blockIdx.y;     // batch
    int tid = threadIdx.x;
    int n = g_clsCnt[b * NC + c];

    // ---- phase A: pair generation for this class ----
    if (n >= 2) {
        const int* gl = g_clsList + (b * NC + c) * TOPK;
        bool cached = (n <= MCACHE);
        if (cached) {
            for (int s = tid; s < n; s += 256) {
                int r = gl[s];
                float4 B = ((const float4*)g_ob)[b * TOPK + r];
                shm.m.sx1[s] = B.x; shm.m.sy1[s] = B.y;
                shm.m.sx2[s] = B.z; shm.m.sy2[s] = B.w;
                shm.m.sar[s] = g_area[b * TOPK + r];
                shm.m.srk[s] = r;
            }
            __syncthreads();
        }
        long long total = (long long)n * (n - 1) / 2;
        long long per = (total + 255) >> 8;
        long long p0 = (long long)tid * per;
        long long p1 = p0 + per; if (p1 > total) p1 = total;
        if (p0 < p1) {
            // find starting row a for p0 (one sqrt + exact fixup), then step incrementally
            float fn = (float)n;
            int a = (int)(fn - 0.5f - sqrtf(fmaxf((fn - 0.5f) * (fn - 0.5f) - 2.0f * (float)p0, 0.0f)));
            if (a < 0) a = 0; if (a > n - 2) a = n - 2;
            while ((long long)(a + 1) * n - (long long)(a + 1) * (a + 2) / 2 <= p0) a++;
            while ((long long)a * n - (long long)a * (a + 1) / 2 > p0) a--;
            long long fa = (long long)a * n - (long long)a * (a + 1) / 2;
            int bq = (int)(p0 - fa) + a + 1;
            for (long long p = p0; p < p1; ++p) {
                bool hit; int r1, r2;
                if (cached) {
                    r1 = shm.m.srk[a]; r2 = shm.m.srk[bq];
                    hit = iou_exceeds(shm.m.sx1[a], shm.m.sy1[a], shm.m.sx2[a], shm.m.sy2[a], shm.m.sar[a],
                                      shm.m.sx1[bq], shm.m.sy1[bq], shm.m.sx2[bq], shm.m.sy2[bq], shm.m.sar[bq]);
                } else {
                    r1 = gl[a]; r2 = gl[bq];
                    int gi = b * TOPK + r1, gj = b * TOPK + r2;
                    float4 A = ((const float4*)g_ob)[gi];
                    float4 B = ((const float4*)g_ob)[gj];
                    hit = iou_exceeds(A.x, A.y, A.z, A.w, g_area[gi],
                                      B.x, B.y, B.z, B.w, g_area[gj]);
                }
                if (hit) {
                    int i = min(r1, r2), j = max(r1, r2);
                    int e = atomicAdd(&g_ecnt[b], 1);
                    if (e < ECAP) g_epair[b * ECAP + e] = ((unsigned)i << 12) | (unsigned)j;
                }
                if (++bq >= n) { ++a; bq = a + 1; }
            }
        }
    }

    // ---- phase B: completion counter; last block of batch b runs suppression ----
    __threadfence();
    __syncthreads();
    if (tid == 0) sLast = (atomicAdd(&g_done[b], 1) == NC - 1);
    __syncthreads();
    if (!sLast) return;
    __threadfence();   // acquire: other blocks' pair writes are now visible

    int nv = g_nvalid[b];
    int cnt = g_ecnt[b];
    if (tid < NWORDS) shm.s.remA[tid] = 0ULL;

    if (cnt <= ECAP) {
        // greedy NMS = unique fixpoint of alive(j) = valid(j) && !exists edge(i,j) alive(i)
        for (int e = tid; e < cnt; e += 256) shm.s.sedge[e] = g_epair[b * ECAP + e];
        __syncthreads();
        for (int round = 0; round <= cnt; ++round) {
            if (tid < NWORDS) shm.s.remB[tid] = 0ULL;
            if (tid == 0) schanged = 0;
            __syncthreads();
            for (int e = tid; e < cnt; e += 256) {
                unsigned k = shm.s.sedge[e];
                int i = (int)(k >> 12);
                if (i < nv && !((shm.s.remA[i >> 6] >> (i & 63)) & 1ULL)) {
                    int j = (int)(k & 4095u);
                    atomicOr(&shm.s.remB[j >> 6], 1ULL << (j & 63));
                }
            }
            __syncthreads();
            if (tid < NWORDS && shm.s.remB[tid] != shm.s.remA[tid]) schanged = 1;  // benign race
            __syncthreads();
            if (!schanged) break;
            if (tid < NWORDS) shm.s.remA[tid] = shm.s.remB[tid];
            __syncthreads();
        }
    } else {
        // fallback (never expected): exact serial greedy from class lists
        if (tid == 0) {
            for (int i = 0; i < nv; ++i) {
                if ((shm.s.remA[i >> 6] >> (i & 63)) & 1ULL) continue;
                int cc = g_selCls[b * TOPK + i];
                int nn = g_clsCnt[b * NC + cc];
                const int* gl2 = g_clsList + (b * NC + cc) * TOPK;
                float4 A = ((const float4*)g_ob)[b * TOPK + i];
                float aA = g_area[b * TOPK + i];
                for (int s = 0; s < nn; ++s) {
                    int j = gl2[s];
                    if (j <= i) continue;
                    if ((shm.s.remA[j >> 6] >> (j & 63)) & 1ULL) continue;
                    float4 B = ((const float4*)g_ob)[b * TOPK + j];
                    if (iou_exceeds(A.x, A.y, A.z, A.w, aA,
                                    B.x, B.y, B.z, B.w, g_area[b * TOPK + j]))
                        shm.s.remA[j >> 6] |= (1ULL << (j & 63));
                }
            }
        }
        __syncthreads();
    }

    if (tid < NWORDS) {
        int lim = nv - tid * 64; if (lim > 64) lim = 64; if (lim < 0) lim = 0;
        ull valid = (lim >= 64) ? ~0ULL : ((lim <= 0) ? 0ULL : ((1ULL << lim) - 1ULL));
        shm.s.keepw[tid] = valid & ~shm.s.remA[tid];
    }
    __syncthreads();

    // ---- fused output compaction ----
    if (tid == 0) {
        int s = 0;
        for (int w = 0; w < NWORDS; ++w) { shm.s.prefix[w] = s; s += __popcll(shm.s.keepw[w]); }
    }
    float* o = out + (size_t)b * MAXDET * 6;
    for (int z = tid; z < MAXDET * 6; z += 256) o[z] = 0.0f;
    __syncthreads();
    for (int i = tid; i < TOPK; i += 256) {
        int w = i >> 6, bt = i & 63;
        if ((shm.s.keepw[w] >> bt) & 1ULL) {
            int rank = shm.s.prefix[w] + __popcll(shm.s.keepw[w] & ((1ULL << bt) - 1ULL));
            if (rank < MAXDET) {
                int gi = b * TOPK + i;
                float* r = o + rank * 6;
                float4 bx = ((const float4*)g_box)[gi];
                r[0] = bx.x; r[1] = bx.y; r[2] = bx.z; r[3] = bx.w;
                r[4] = g_selScore[gi];
                r[5] = (float)g_selCls[gi];
            }
        }
    }
}

// ---------------- launch ---------------------------------------------------------------
extern "C" void kernel_launch(void* const* d_in, const int* in_sizes, int n_in,
                              void* d_out, int out_size) {
    const float* pred = (const float*)d_in[0];
    float* out = (float*)d_out;

    // opt-in to >48KB dynamic shared (attribute set, not an allocation; capture-safe)
    cudaFuncSetAttribute(k_select, cudaFuncAttributeMaxDynamicSharedMemorySize, SELECT_SMEM);

    // 1) conf / argmax / order key : float4-staged, REDUX max + ballot argmax
    {
        int groups = (BATCH * NPRED) / 12;   // 403200/12 = 33600 exactly
        k_prep<<<groups, 384>>>((const float4*)pred);
    }
    // 2) exact top-4096 per batch (histogram threshold + bucket rank) + fused gather
    k_select<<<BATCH, 1024, SELECT_SMEM>>>(pred);
    // 3) per-class pairwise IoU -> pairs; last block per batch: suppression + output
    {
        dim3 g(NC, BATCH);
        k_mask<<<g, 256>>>(out);
    }
}

// round 16
// speedup vs baseline: 1.3607x; 1.3607x over previous
#include <cuda_runtime.h>
#include <cuda_bf16.h>
#include <cstdint>

#define BATCH   16
#define NPRED   25200
#define NC      80
#define STRIDE  85
#define TOPK    4096
#define MAXDET  1000
#define NWORDS  64            // TOPK/64
#define NITEMS  25            // ceil(NPRED/1024)
#define ECAP    8192          // per-batch suppression-pair capacity (fast path)
#define MCACHE  1024          // k_mask shared box-cache capacity
#define CONF_THRES 0.25f
#define IOU_THRES  0.45f
#define MAX_WH     7680.0f

#define U_BASE    0xBE800000u   // order-key of conf==0.25 (exclusive lower bound)
#define U_INVALID 0x407FFFFFu   // order-key of s==-1.0

typedef unsigned long long ull;

// ---------------- scratch (no allocation allowed; __device__ globals) ----------------
__device__ unsigned  g_u[BATCH * NPRED];        // order key (score fully recoverable)
__device__ int       g_cls[BATCH * NPRED];      // argmax class
__device__ float     g_selScore[BATCH * TOPK];
__device__ int       g_selCls[BATCH * TOPK];
__device__ float     g_box[BATCH * TOPK * 4];   // xyxy (no offset)
__device__ float     g_ob[BATCH * TOPK * 4];    // offset boxes
__device__ float     g_area[BATCH * TOPK];      // area of offset box
__device__ int       g_nvalid[BATCH];
__device__ int       g_clsCnt[BATCH * NC];      // per-class member counts
__device__ int       g_clsList[BATCH * NC * TOPK / 64 * 64]; // capacity TOPK per class
__device__ int       g_ecnt[BATCH];             // suppression pair counts
__device__ unsigned  g_epair[BATCH * ECAP];     // packed (i<<12)|j, i<j
__device__ int       g_done[BATCH];             // per-batch mask-block completion count

// -------- kernel 1: conf / argmax / order-key (shuffle-max + ballot argmax) ----------
// 12 rows * 85 floats = 1020 floats = 255 float4, and group base is 16B-aligned.
// Products obj*cls are >= 0, so their float bits compare as unsigned. Max is a
// 5-step shuffle-IMNMX tree (pipelined, 2 instr/step); the exact first-index
// argmax is recovered by equality ballots over the identical fl(obj*cls_c)
// values the reference computes (lowest class index on ties).
__global__ void __launch_bounds__(384) k_prep(const float4* __restrict__ pred4) {
    __shared__ float4 buf4[255];
    int grp = blockIdx.x;
    int t = threadIdx.x;
    if (t < 255) buf4[t] = pred4[grp * 255 + t];
    __syncthreads();
    const float* buf = (const float*)buf4;
    int w = t >> 5, lane = t & 31;          // 12 warps, one row each
    const float* r = buf + w * 85;
    float obj = r[4];
    float p0 = __fmul_rn(obj, r[5 + lane]);          // classes 0..31
    float p1 = __fmul_rn(obj, r[37 + lane]);         // classes 32..63
    float p2 = (lane < 16) ? __fmul_rn(obj, r[69 + lane]) : 0.0f;  // classes 64..79
    unsigned b0 = __float_as_uint(p0);
    unsigned b1 = __float_as_uint(p1);
    unsigned b2 = __float_as_uint(p2);
    unsigned m = max(b0, max(b1, b2));
    #pragma unroll
    for (int o = 16; o; o >>= 1)
        m = max(m, __shfl_xor_sync(0xFFFFFFFFu, m, o));   // pipelined max tree
    unsigned e0 = __ballot_sync(0xFFFFFFFFu, b0 == m);
    unsigned e1 = __ballot_sync(0xFFFFFFFFu, b1 == m);
    unsigned e2 = __ballot_sync(0xFFFFFFFFu, b2 == m) & 0xFFFFu;  // mask padding
    if (lane == 0) {
        int bi = e0 ? (__ffs(e0) - 1) : (e1 ? (32 + __ffs(e1) - 1) : (64 + __ffs(e2) - 1));
        float s = __uint_as_float(m);
        s = (s > CONF_THRES) ? s : -1.0f;
        unsigned ub = __float_as_uint(s);
        unsigned uo = (ub & 0x80000000u) ? ~ub : (ub | 0x80000000u); // ascending order map
        int row = grp * 12 + w;
        g_u[row] = uo; g_cls[row] = bi;
    }
}

// ---------------- kernel 2: top-4096 (histogram threshold + bucket rank) -------------
__device__ __forceinline__ ull shfl_xor_u64(ull x, int m) {
    unsigned lo = __shfl_xor_sync(0xFFFFFFFFu, (unsigned)x, m);
    unsigned hi = __shfl_xor_sync(0xFFFFFFFFu, (unsigned)(x >> 32), m);
    return ((ull)hi << 32) | lo;
}

// inclusive suffix scan over 1024 threads (3 barriers, shfl-based)
__device__ __forceinline__ int blockSuffixScan1024(int v, int tid, int* warpBuf) {
    int lane = tid & 31, w = tid >> 5;
    __syncthreads();     // protect warpBuf from previous use
    #pragma unroll
    for (int off = 1; off < 32; off <<= 1) {
        int t = __shfl_down_sync(0xFFFFFFFFu, v, off);
        if (lane + off < 32) v += t;
    }
    if (lane == 0) warpBuf[w] = v;   // whole-warp sum
    __syncthreads();
    if (w == 0) {
        int s = warpBuf[lane];
        #pragma unroll
        for (int off = 1; off < 32; off <<= 1) {
            int t = __shfl_down_sync(0xFFFFFFFFu, s, off);
            if (lane + off < 32) s += t;
        }
        warpBuf[lane] = s;           // inclusive suffix over warp sums
    }
    __syncthreads();
    int later = (w < 31) ? warpBuf[w + 1] : 0;
    return v + later;
}

#define NIT_U   16
#define NIT_I   15
#define CNT_TOTAL 64
// dynamic smem layout: keys[4096] ull (32KB) | selC[4096] int (16KB) |
//                      fill[4096] int (16KB) | grpSuf[1024] int (4KB)  = 69632 B
#define SELECT_SMEM 69632

extern __shared__ char dynsmem[];

__global__ void __launch_bounds__(1024) k_select(const float* __restrict__ pred) {
    int b = blockIdx.x;
    int tid = threadIdx.x;
    int lane = tid & 31;
    const unsigned* u = g_u + b * NPRED;
    ull* keys   = (ull*)dynsmem;                 // 4096 keys
    int* selC   = (int*)(dynsmem + 32768);       // hist -> selected counts
    int* fill   = (int*)(dynsmem + 49152);       // bucket fill counters
    int* grpSuf = (int*)(dynsmem + 65536);       // 1024 group suffix sums
    __shared__ int cnts[CNT_TOTAL];
    __shared__ int warpBuf[32];
    __shared__ int sB, sNeed, sBinCnt, sMode, sG, sMax;
    __shared__ ull sKstar;
    __shared__ int scnt, svalid;

    // zero per-batch side state
    if (tid < NC) g_clsCnt[b * NC + tid] = 0;
    if (tid == 0) { g_ecnt[b] = 0; g_done[b] = 0; scnt = 0; svalid = 0; sMax = 0; }
    if (tid < CNT_TOTAL) cnts[tid] = 0;

    // ---- load all keys into registers (one pass over memory) ----
    unsigned uv[NITEMS];
    #pragma unroll
    for (int k = 0; k < NITEMS; ++k) {
        int i = k * 1024 + tid;
        uv[k] = (i < NPRED) ? u[i] : 0u;   // padding u=0: never matches anything
    }

    // ---- phase 1: 4096-bin histogram of valid keys ----
    #pragma unroll
    for (int h = tid; h < 4096; h += 1024) selC[h] = 0;
    __syncthreads();
    #pragma unroll
    for (int k = 0; k < NITEMS; ++k) {
        unsigned k0 = uv[k];
        if (k0 > U_BASE) {
            int bin = (int)((k0 - U_BASE - 1u) >> 12);
            if (bin > 4095) bin = 4095;
            atomicAdd(&selC[bin], 1);
        }
    }
    __syncthreads();

    // ---- phase 2: suffix-scan over 1024 groups of 4 bins (shfl-based) ----
    {
        int g4 = tid * 4;
        int v = selC[g4] + selC[g4 + 1] + selC[g4 + 2] + selC[g4 + 3];
        int r = blockSuffixScan1024(v, tid, warpBuf);
        grpSuf[tid] = r;
        __syncthreads();
    }
    int totalValid = grpSuf[0];
    if (totalValid >= TOPK) {
        if (grpSuf[tid] >= TOPK && (tid == 1023 || grpSuf[tid + 1] < TOPK)) sG = tid;
        __syncthreads();
        if (tid == 0) {
            int g = sG;
            int c2 = (g < 1023) ? grpSuf[g + 1] : 0;
            int Bst = g * 4, cntGt = c2;
            for (int bb = g * 4 + 3; bb >= g * 4; --bb) {
                if (c2 + selC[bb] >= TOPK) { Bst = bb; cntGt = c2; break; }
                c2 += selC[bb];
            }
            sB = Bst; sNeed = TOPK - cntGt; sBinCnt = selC[Bst]; sMode = 0;
        }
    } else {
        if (tid == 0) { sB = -1; sNeed = TOPK - totalValid; sBinCnt = NPRED - totalValid; sMode = 1; }
    }
    __syncthreads();
    int Bst = sB, need = sNeed, binCnt = sBinCnt, mode = sMode;
    __syncthreads();

    // ---- phase 3: exact threshold key K* ----
    if (binCnt <= TOPK) {
        // gather candidate-bin keys into keys[], tiny bitonic, K* = need-th largest
        if (tid == 0) scnt = 0;
        __syncthreads();
        #pragma unroll
        for (int k = 0; k < NITEMS; ++k) {
            int i = k * 1024 + tid;
            unsigned k0 = uv[k];
            bool m;
            if (mode == 0) {
                int bin = -1;
                if (k0 > U_BASE) {
                    bin = (int)((k0 - U_BASE - 1u) >> 12);
                    if (bin > 4095) bin = 4095;
                }
                m = (bin == Bst);
            } else {
                m = (k0 == U_INVALID) && (i < NPRED);
            }
            if (m) {
                int p = atomicAdd(&scnt, 1);
                if (p < TOPK) keys[p] = ((ull)k0 << 32) | (unsigned)(~i);
            }
        }
        __syncthreads();
        int cnt = scnt;
        int n = 2; while (n < cnt) n <<= 1;
        for (int e = tid; e < n; e += 1024) if (e >= cnt) keys[e] = 0ULL;
        __syncthreads();
        for (int k = 2; k <= n; k <<= 1) {
            for (int j = k >> 1; j >= 1; j >>= 1) {
                for (int x = tid; x < n; x += 1024) {
                    int l = x ^ j;
                    if (l > x) {
                        bool desc = ((x & k) == 0);
                        ull a = keys[x], c = keys[l];
                        if (desc ? (a < c) : (a > c)) { keys[x] = c; keys[l] = a; }
                    }
                }
                __syncthreads();
            }
        }
        if (tid == 0) sKstar = keys[need - 1];
        __syncthreads();
    } else {
        // fallback (never expected): 2-bit search + tie search
        unsigned U = 0u;
        #pragma unroll
        for (int it = 0; it < NIT_U; ++it) {
            int s = 30 - 2 * it;
            unsigned c1t = U + (1u << s);
            int c1 = 0, c2 = 0, c3 = 0;
            #pragma unroll
            for (int k = 0; k < NITEMS; ++k) {
                unsigned k0 = uv[k];
                if (k0 >= c1t) {
                    unsigned w = (k0 - U) >> s;
                    c1++;
                    if (w >= 2) c2++;
                    if (w >= 3) c3++;
                }
            }
            c1 = __reduce_add_sync(0xFFFFFFFFu, c1);
            c2 = __reduce_add_sync(0xFFFFFFFFu, c2);
            c3 = __reduce_add_sync(0xFFFFFFFFu, c3);
            if (lane == 0) {
                atomicAdd(&cnts[it * 3 + 0], c1);
                atomicAdd(&cnts[it * 3 + 1], c2);
                atomicAdd(&cnts[it * 3 + 2], c3);
            }
            __syncthreads();
            int t1 = cnts[it * 3 + 0], t2 = cnts[it * 3 + 1], t3 = cnts[it * 3 + 2];
            unsigned v = (t3 >= TOPK) ? 3u : (t2 >= TOPK) ? 2u : (t1 >= TOPK) ? 1u : 0u;
            U |= v << s;
        }
        unsigned ustar = U;
        {
            int c = 0;
            #pragma unroll
            for (int k = 0; k < NITEMS; ++k) c += (uv[k] > ustar);
            c = __reduce_add_sync(0xFFFFFFFFu, c);
            if (lane == 0) atomicAdd(&cnts[48], c);
            __syncthreads();
        }
        int need2 = TOPK - cnts[48];
        int M = 0;
        #pragma unroll
        for (int it = 0; it < NIT_I; ++it) {
            int bit = 14 - it;
            int candi = M | (1 << bit);
            int c = 0;
            #pragma unroll
            for (int k = 0; k < NITEMS; ++k) {
                int i = k * 1024 + tid;
                if (uv[k] == ustar && i < candi && i < NPRED) c++;
            }
            c = __reduce_add_sync(0xFFFFFFFFu, c);
            if (lane == 0) atomicAdd(&cnts[49 + it], c);
            __syncthreads();
            if (cnts[49 + it] < need2) M = candi;
        }
        if (tid == 0) sKstar = ((ull)ustar << 32) | (unsigned)(~M);
        __syncthreads();
    }
    ull Kstar = sKstar;
    __syncthreads();

    // ---- phase 4: selected-count conversion + bucket-size guard ----
    bool fastOK = false;
    if (mode == 0) {
        #pragma unroll
        for (int h = tid; h < 4096; h += 1024) {
            if (h < Bst) selC[h] = 0;
            else if (h == Bst) selC[h] = need;
        }
        __syncthreads();
        int mymax = 0;
        #pragma unroll
        for (int h = tid; h < 4096; h += 1024) if (selC[h] > mymax) mymax = selC[h];
        mymax = __reduce_max_sync(0xFFFFFFFFu, mymax);
        if (lane == 0) atomicMax(&sMax, mymax);
        __syncthreads();
        fastOK = (sMax <= 64);
    }

    if (fastOK) {
        // ---- phase 5a: suffix-scan of selected counts, scatter to final slots ----
        {
            int g4 = tid * 4;
            int v = selC[g4] + selC[g4 + 1] + selC[g4 + 2] + selC[g4 + 3];
            int r = blockSuffixScan1024(v, tid, warpBuf);
            grpSuf[tid] = r;
        }
        #pragma unroll
        for (int h = tid; h < 4096; h += 1024) fill[h] = 0;
        __syncthreads();
        #pragma unroll
        for (int k = 0; k < NITEMS; ++k) {
            int i = k * 1024 + tid;
            unsigned k0 = uv[k];
            ull key = ((ull)k0 << 32) | (unsigned)(~i);
            if (i < NPRED && key >= Kstar) {
                int bin = (int)((k0 - U_BASE - 1u) >> 12);
                if (bin > 4095) bin = 4095;
                int g = bin >> 2;
                int base = (g < 1023) ? grpSuf[g + 1] : 0;
                for (int b2 = (g << 2) + 3; b2 > bin; --b2) base += selC[b2];
                int slot = base + atomicAdd(&fill[bin], 1);
                keys[slot] = key;
            }
        }
        __syncthreads();
        // ---- per-bucket insertion sort (descending; buckets <= 64) ----
        for (int bin = tid; bin < 4096; bin += 1024) {
            int cnt = selC[bin];
            if (cnt > 1) {
                int g = bin >> 2;
                int base = (g < 1023) ? grpSuf[g + 1] : 0;
                for (int b2 = (g << 2) + 3; b2 > bin; --b2) base += selC[b2];
                for (int a = 1; a < cnt; ++a) {
                    ull kv = keys[base + a];
                    int q = a - 1;
                    while (q >= 0 && keys[base + q] < kv) { keys[base + q + 1] = keys[base + q]; --q; }
                    keys[base + q + 1] = kv;
                }
            }
        }
        __syncthreads();
    } else {
        // ---- phase 5b (fallback): gather + full hybrid bitonic ----
        if (tid == 0) scnt = 0;
        __syncthreads();
        #pragma unroll
        for (int k = 0; k < NITEMS; ++k) {
            int i = k * 1024 + tid;
            ull key = ((ull)uv[k] << 32) | (unsigned)(~i);
            bool m = (i < NPRED) && (key >= Kstar);
            unsigned act = __ballot_sync(0xFFFFFFFFu, m);
            if (m) {
                int leader = __ffs(act) - 1;
                int rank = __popc(act & ((1u << lane) - 1u));
                int base;
                if (lane == leader) base = atomicAdd(&scnt, __popc(act));
                base = __shfl_sync(act, base, leader);
                int pos = base + rank;
                if (pos < TOPK) keys[pos] = key;
            }
        }
        __syncthreads();
        ull v[4];
        #pragma unroll
        for (int e = 0; e < 4; ++e) v[e] = keys[tid * 4 + e];
        for (int k = 2; k <= TOPK; k <<= 1) {
            for (int j = k >> 1; j >= 1; j >>= 1) {
                if (j >= 128) {
                    #pragma unroll
                    for (int e = 0; e < 4; ++e) keys[tid * 4 + e] = v[e];
                    __syncthreads();
                    #pragma unroll
                    for (int e = 0; e < 4; ++e) {
                        int idx = tid * 4 + e;
                        ull pv = keys[idx ^ j];
                        bool d = ((idx & k) == 0);
                        bool lower = ((idx & j) == 0);
                        bool keepmax = (d == lower);
                        ull mx = (v[e] > pv) ? v[e] : pv;
                        ull mn = (v[e] > pv) ? pv : v[e];
                        v[e] = keepmax ? mx : mn;
                    }
                    __syncthreads();
                } else if (j >= 4) {
                    int dl = j >> 2;
                    #pragma unroll
                    for (int e = 0; e < 4; ++e) {
                        ull pv = shfl_xor_u64(v[e], dl);
                        int idx = tid * 4 + e;
                        bool d = ((idx & k) == 0);
                        bool lower = ((tid & dl) == 0);
                        bool keepmax = (d == lower);
                        ull mx = (v[e] > pv) ? v[e] : pv;
                        ull mn = (v[e] > pv) ? pv : v[e];
                        v[e] = keepmax ? mx : mn;
                    }
                } else {
                    #pragma unroll
                    for (int e = 0; e < 4; ++e) {
                        if ((e & j) == 0) {
                            int idx = tid * 4 + e;
                            bool d = ((idx & k) == 0);
                            ull a = v[e], c2 = v[e + j];
                            if (d ? (a < c2) : (a > c2)) { v[e] = c2; v[e + j] = a; }
                        }
                    }
                }
            }
        }
        #pragma unroll
        for (int e = 0; e < 4; ++e) keys[tid * 4 + e] = v[e];
        __syncthreads();
    }

    // ---- emit + fused gather of boxes / classes / areas + class bucketing ----
    int lv = 0;
    #pragma unroll
    for (int e = 0; e < 4; ++e) {
        int rank = tid * 4 + e;
        ull key = keys[rank];
        unsigned k0 = (unsigned)(key >> 32);
        int i = (int)(~(unsigned)(key & 0xFFFFFFFFull));
        int gi = b * TOPK + rank;
        // s exactly recovered from the order key (mapping is invertible)
        float s = (k0 & 0x80000000u) ? __uint_as_float(k0 & 0x7FFFFFFFu) : -1.0f;
        g_selScore[gi] = s;
        lv += (s > 0.0f);
        int ci = g_cls[b * NPRED + i];
        g_selCls[gi] = ci;
        int slot = atomicAdd(&g_clsCnt[b * NC + ci], 1);
        g_clsList[(b * NC + ci) * TOPK + slot] = rank;
        const float* p = pred + ((size_t)b * NPRED + i) * STRIDE;
        float xc = p[0], yc = p[1], w = p[2], h = p[3];
        float hw = __fmul_rn(w, 0.5f), hh = __fmul_rn(h, 0.5f);
        float x1 = __fsub_rn(xc, hw), y1 = __fsub_rn(yc, hh);
        float x2 = __fadd_rn(xc, hw), y2 = __fadd_rn(yc, hh);
        float off = __fmul_rn((float)ci, MAX_WH);
        float ox1 = __fadd_rn(x1, off), oy1 = __fadd_rn(y1, off);
        float ox2 = __fadd_rn(x2, off), oy2 = __fadd_rn(y2, off);
        ((float4*)g_box)[gi] = make_float4(x1, y1, x2, y2);
        ((float4*)g_ob)[gi]  = make_float4(ox1, oy1, ox2, oy2);
        g_area[gi] = __fmul_rn(__fsub_rn(ox2, ox1), __fsub_rn(oy2, oy1));
    }
    lv = __reduce_add_sync(0xFFFFFFFFu, lv);
    if (lane == 0) atomicAdd(&svalid, lv);
    __syncthreads();
    if (tid == 0) g_nvalid[b] = svalid;
}

// -------- kernel 3: per-class IoU -> pairs, then LAST block per batch suppresses -----
__device__ __forceinline__ bool iou_exceeds(float ax1, float ay1, float ax2, float ay2,
                                            float aA,
                                            float bx1, float by1, float bx2, float by2,
                                            float aB) {
    float ltx = fmaxf(ax1, bx1);
    float lty = fmaxf(ay1, by1);
    float rbx = fminf(ax2, bx2);
    float rby = fminf(ay2, by2);
    float wv = fmaxf(__fsub_rn(rbx, ltx), 0.0f);
    float hv = fmaxf(__fsub_rn(rby, lty), 0.0f);
    float inter = __fmul_rn(wv, hv);
    if (inter <= 0.0f) return false;
    float denom = __fadd_rn(__fsub_rn(__fadd_rn(aA, aB), inter), 1e-7f);
    return __fdiv_rn(inter, denom) > IOU_THRES;
}

struct MaskShm {
    float sx1[MCACHE], sy1[MCACHE], sx2[MCACHE], sy2[MCACHE], sar[MCACHE];
    int   srk[MCACHE];
};
struct SupShm {
    unsigned sedge[ECAP];
    ull remA[NWORDS], remB[NWORDS], keepw[NWORDS];
    int prefix[NWORDS];
};

__global__ void __launch_bounds__(256) k_mask(float* __restrict__ out) {
    __shared__ union { MaskShm m; SupShm s; } shm;
    __shared__ int sLast, schanged;
    int c = blockIdx.x;     // class
    int b = blockIdx.y;     // batch
    int tid = threadIdx.x;
    int n = g_clsCnt[b * NC + c];

    // ---- phase A: pair generation for this class ----
    if (n >= 2) {
        const int* gl = g_clsList + (b * NC + c) * TOPK;
        bool cached = (n <= MCACHE);
        if (cached) {
            for (int s = tid; s < n; s += 256) {
                int r = gl[s];
                float4 B = ((const float4*)g_ob)[b * TOPK + r];
                shm.m.sx1[s] = B.x; shm.m.sy1[s] = B.y;
                shm.m.sx2[s] = B.z; shm.m.sy2[s] = B.w;
                shm.m.sar[s] = g_area[b * TOPK + r];
                shm.m.srk[s] = r;
            }
            __syncthreads();
        }
        long long total = (long long)n * (n - 1) / 2;
        long long per = (total + 255) >> 8;
        long long p0 = (long long)tid * per;
        long long p1 = p0 + per; if (p1 > total) p1 = total;
        if (p0 < p1) {
            // find starting row a for p0 (one sqrt + exact fixup), then step incrementally
            float fn = (float)n;
            int a = (int)(fn - 0.5f - sqrtf(fmaxf((fn - 0.5f) * (fn - 0.5f) - 2.0f * (float)p0, 0.0f)));
            if (a < 0) a = 0; if (a > n - 2) a = n - 2;
            while ((long long)(a + 1) * n - (long long)(a + 1) * (a + 2) / 2 <= p0) a++;
            while ((long long)a * n - (long long)a * (a + 1) / 2 > p0) a--;
            long long fa = (long long)a * n - (long long)a * (a + 1) / 2;
            int bq = (int)(p0 - fa) + a + 1;
            for (long long p = p0; p < p1; ++p) {
                bool hit; int r1, r2;
                if (cached) {
                    r1 = shm.m.srk[a]; r2 = shm.m.srk[bq];
                    hit = iou_exceeds(shm.m.sx1[a], shm.m.sy1[a], shm.m.sx2[a], shm.m.sy2[a], shm.m.sar[a],
                                      shm.m.sx1[bq], shm.m.sy1[bq], shm.m.sx2[bq], shm.m.sy2[bq], shm.m.sar[bq]);
                } else {
                    r1 = gl[a]; r2 = gl[bq];
                    int gi = b * TOPK + r1, gj = b * TOPK + r2;
                    float4 A = ((const float4*)g_ob)[gi];
                    float4 B = ((const float4*)g_ob)[gj];
                    hit = iou_exceeds(A.x, A.y, A.z, A.w, g_area[gi],
                                      B.x, B.y, B.z, B.w, g_area[gj]);
                }
                if (hit) {
                    int i = min(r1, r2), j = max(r1, r2);
                    int e = atomicAdd(&g_ecnt[b], 1);
                    if (e < ECAP) g_epair[b * ECAP + e] = ((unsigned)i << 12) | (unsigned)j;
                }
                if (++bq >= n) { ++a; bq = a + 1; }
            }
        }
    }

    // ---- phase B: completion counter; last block of batch b runs suppression ----
    __threadfence();
    __syncthreads();
    if (tid == 0) sLast = (atomicAdd(&g_done[b], 1) == NC - 1);
    __syncthreads();
    if (!sLast) return;
    __threadfence();   // acquire: other blocks' pair writes are now visible

    int nv = g_nvalid[b];
    int cnt = g_ecnt[b];
    if (tid < NWORDS) shm.s.remA[tid] = 0ULL;

    if (cnt <= ECAP) {
        // greedy NMS = unique fixpoint of alive(j) = valid(j) && !exists edge(i,j) alive(i)
        for (int e = tid; e < cnt; e += 256) shm.s.sedge[e] = g_epair[b * ECAP + e];
        __syncthreads();
        for (int round = 0; round <= cnt; ++round) {
            if (tid < NWORDS) shm.s.remB[tid] = 0ULL;
            if (tid == 0) schanged = 0;
            __syncthreads();
            for (int e = tid; e < cnt; e += 256) {
                unsigned k = shm.s.sedge[e];
                int i = (int)(k >> 12);
                if (i < nv && !((shm.s.remA[i >> 6] >> (i & 63)) & 1ULL)) {
                    int j = (int)(k & 4095u);
                    atomicOr(&shm.s.remB[j >> 6], 1ULL << (j & 63));
                }
            }
            __syncthreads();
            if (tid < NWORDS && shm.s.remB[tid] != shm.s.remA[tid]) schanged = 1;  // benign race
            __syncthreads();
            if (!schanged) break;
            if (tid < NWORDS) shm.s.remA[tid] = shm.s.remB[tid];
            __syncthreads();
        }
    } else {
        // fallback (never expected): exact serial greedy from class lists
        if (tid == 0) {
            for (int i = 0; i < nv; ++i) {
                if ((shm.s.remA[i >> 6] >> (i & 63)) & 1ULL) continue;
                int cc = g_selCls[b * TOPK + i];
                int nn = g_clsCnt[b * NC + cc];
                const int* gl2 = g_clsList + (b * NC + cc) * TOPK;
                float4 A = ((const float4*)g_ob)[b * TOPK + i];
                float aA = g_area[b * TOPK + i];
                for (int s = 0; s < nn; ++s) {
                    int j = gl2[s];
                    if (j <= i) continue;
                    if ((shm.s.remA[j >> 6] >> (j & 63)) & 1ULL) continue;
                    float4 B = ((const float4*)g_ob)[b * TOPK + j];
                    if (iou_exceeds(A.x, A.y, A.z, A.w, aA,
                                    B.x, B.y, B.z, B.w, g_area[b * TOPK + j]))
                        shm.s.remA[j >> 6] |= (1ULL << (j & 63));
                }
            }
        }
        __syncthreads();
    }

    if (tid < NWORDS) {
        int lim = nv - tid * 64; if (lim > 64) lim = 64; if (lim < 0) lim = 0;
        ull valid = (lim >= 64) ? ~0ULL : ((lim <= 0) ? 0ULL : ((1ULL << lim) - 1ULL));
        shm.s.keepw[tid] = valid & ~shm.s.remA[tid];
    }
    __syncthreads();

    // ---- fused output compaction ----
    if (tid == 0) {
        int s = 0;
        for (int w = 0; w < NWORDS; ++w) { shm.s.prefix[w] = s; s += __popcll(shm.s.keepw[w]); }
    }
    float* o = out + (size_t)b * MAXDET * 6;
    for (int z = tid; z < MAXDET * 6; z += 256) o[z] = 0.0f;
    __syncthreads();
    for (int i = tid; i < TOPK; i += 256) {
        int w = i >> 6, bt = i & 63;
        if ((shm.s.keepw[w] >> bt) & 1ULL) {
            int rank = shm.s.prefix[w] + __popcll(shm.s.keepw[w] & ((1ULL << bt) - 1ULL));
            if (rank < MAXDET) {
                int gi = b * TOPK + i;
                float* r = o + rank * 6;
                float4 bx = ((const float4*)g_box)[gi];
                r[0] = bx.x; r[1] = bx.y; r[2] = bx.z; r[3] = bx.w;
                r[4] = g_selScore[gi];
                r[5] = (float)g_selCls[gi];
            }
        }
    }
}

// ---------------- launch ---------------------------------------------------------------
extern "C" void kernel_launch(void* const* d_in, const int* in_sizes, int n_in,
                              void* d_out, int out_size) {
    const float* pred = (const float*)d_in[0];
    float* out = (float*)d_out;

    // opt-in to >48KB dynamic shared (attribute set, not an allocation; capture-safe)
    cudaFuncSetAttribute(k_select, cudaFuncAttributeMaxDynamicSharedMemorySize, SELECT_SMEM);

    // 1) conf / argmax / order key : float4-staged, shuffle-max + ballot argmax
    {
        int groups = (BATCH * NPRED) / 12;   // 403200/12 = 33600 exactly
        k_prep<<<groups, 384>>>((const float4*)pred);
    }
    // 2) exact top-4096 per batch (histogram threshold + bucket rank) + fused gather
    k_select<<<BATCH, 1024, SELECT_SMEM>>>(pred);
    // 3) per-class pairwise IoU -> pairs; last block per batch: suppression + output
    {
        dim3 g(NC, BATCH);
        k_mask<<<g, 256>>>(out);
    }
}

// round 17
// speedup vs baseline: 1.5635x; 1.1491x over previous
#include <cuda_runtime.h>
#include <cuda_bf16.h>
#include <cstdint>

#define BATCH   16
#define NPRED   25200
#define NC      80
#define STRIDE  85
#define TOPK    4096
#define MAXDET  1000
#define NWORDS  64            // TOPK/64
#define NITEMS  25            // ceil(NPRED/1024)
#define ECAP    8192          // per-batch suppression-pair capacity (fast path)
#define MCACHE  1024          // k_mask shared box-cache capacity
#define CONF_THRES 0.25f
#define IOU_THRES  0.45f
#define MAX_WH     7680.0f

#define U_BASE    0xBE800000u   // order-key of conf==0.25 (exclusive lower bound)
#define U_INVALID 0x407FFFFFu   // order-key of s==-1.0

typedef unsigned long long ull;

// ---------------- scratch (no allocation allowed; __device__ globals) ----------------
__device__ unsigned  g_u[BATCH * NPRED];        // order key (score fully recoverable)
__device__ int       g_cls[BATCH * NPRED];      // argmax class
__device__ float     g_selScore[BATCH * TOPK];
__device__ int       g_selCls[BATCH * TOPK];
__device__ float     g_box[BATCH * TOPK * 4];   // xyxy (no offset)
__device__ float     g_ob[BATCH * TOPK * 4];    // offset boxes
__device__ float     g_area[BATCH * TOPK];      // area of offset box
__device__ int       g_nvalid[BATCH];
__device__ int       g_clsCnt[BATCH * NC];      // per-class member counts
__device__ int       g_clsList[BATCH * NC * TOPK / 64 * 64]; // capacity TOPK per class
__device__ int       g_ecnt[BATCH];             // suppression pair counts
__device__ unsigned  g_epair[BATCH * ECAP];     // packed (i<<12)|j, i<j
__device__ int       g_done[BATCH];             // per-batch mask-block completion count

// -------- kernel 1: conf / argmax / order-key (2 rows/warp, interleaved chains) ------
// 24 rows * 85 floats = 2040 floats = 510 float4, and group base is 16B-aligned.
// Products obj*cls are >= 0, so float order == unsigned-bit order. Each warp
// computes TWO rows with interleaved shuffle-max trees (two independent
// dependency chains hide the ~26-cycle SHFL latency); the exact first-index
// argmax is recovered by equality ballots over the identical fl(obj*cls_c)
// values the reference computes (lowest class index on ties).
__global__ void __launch_bounds__(384) k_prep(const float4* __restrict__ pred4) {
    __shared__ float4 buf4[510];
    int grp = blockIdx.x;
    int t = threadIdx.x;
    buf4[t] = pred4[grp * 510 + t];
    if (t < 126) buf4[384 + t] = pred4[grp * 510 + 384 + t];
    __syncthreads();
    const float* buf = (const float*)buf4;
    int w = t >> 5, lane = t & 31;          // 12 warps, two rows each
    const float* rA = buf + (2 * w) * 85;
    const float* rB = buf + (2 * w + 1) * 85;
    float objA = rA[4];
    float objB = rB[4];
    float a0 = __fmul_rn(objA, rA[5 + lane]);
    float b0f = __fmul_rn(objB, rB[5 + lane]);
    float a1 = __fmul_rn(objA, rA[37 + lane]);
    float b1f = __fmul_rn(objB, rB[37 + lane]);
    float a2 = (lane < 16) ? __fmul_rn(objA, rA[69 + lane]) : 0.0f;
    float b2f = (lane < 16) ? __fmul_rn(objB, rB[69 + lane]) : 0.0f;
    unsigned ua0 = __float_as_uint(a0), ub0 = __float_as_uint(b0f);
    unsigned ua1 = __float_as_uint(a1), ub1 = __float_as_uint(b1f);
    unsigned ua2 = __float_as_uint(a2), ub2 = __float_as_uint(b2f);
    unsigned mA = max(ua0, max(ua1, ua2));
    unsigned mB = max(ub0, max(ub1, ub2));
    #pragma unroll
    for (int o = 16; o; o >>= 1) {          // two interleaved max trees
        unsigned sA = __shfl_xor_sync(0xFFFFFFFFu, mA, o);
        unsigned sB = __shfl_xor_sync(0xFFFFFFFFu, mB, o);
        mA = max(mA, sA);
        mB = max(mB, sB);
    }
    unsigned eA0 = __ballot_sync(0xFFFFFFFFu, ua0 == mA);
    unsigned eB0 = __ballot_sync(0xFFFFFFFFu, ub0 == mB);
    unsigned eA1 = __ballot_sync(0xFFFFFFFFu, ua1 == mA);
    unsigned eB1 = __ballot_sync(0xFFFFFFFFu, ub1 == mB);
    unsigned eA2 = __ballot_sync(0xFFFFFFFFu, ua2 == mA) & 0xFFFFu;
    unsigned eB2 = __ballot_sync(0xFFFFFFFFu, ub2 == mB) & 0xFFFFu;
    if (lane == 0) {
        int rowA = grp * 24 + 2 * w;
        {
            int bi = eA0 ? (__ffs(eA0) - 1) : (eA1 ? (32 + __ffs(eA1) - 1) : (64 + __ffs(eA2) - 1));
            float s = __uint_as_float(mA);
            s = (s > CONF_THRES) ? s : -1.0f;
            unsigned ub = __float_as_uint(s);
            unsigned uo = (ub & 0x80000000u) ? ~ub : (ub | 0x80000000u);
            g_u[rowA] = uo; g_cls[rowA] = bi;
        }
        {
            int bi = eB0 ? (__ffs(eB0) - 1) : (eB1 ? (32 + __ffs(eB1) - 1) : (64 + __ffs(eB2) - 1));
            float s = __uint_as_float(mB);
            s = (s > CONF_THRES) ? s : -1.0f;
            unsigned ub = __float_as_uint(s);
            unsigned uo = (ub & 0x80000000u) ? ~ub : (ub | 0x80000000u);
            g_u[rowA + 1] = uo; g_cls[rowA + 1] = bi;
        }
    }
}

// ---------------- kernel 2: top-4096 (histogram threshold + bucket rank) -------------
__device__ __forceinline__ ull shfl_xor_u64(ull x, int m) {
    unsigned lo = __shfl_xor_sync(0xFFFFFFFFu, (unsigned)x, m);
    unsigned hi = __shfl_xor_sync(0xFFFFFFFFu, (unsigned)(x >> 32), m);
    return ((ull)hi << 32) | lo;
}

// inclusive suffix scan over 1024 threads (3 barriers, shfl-based)
__device__ __forceinline__ int blockSuffixScan1024(int v, int tid, int* warpBuf) {
    int lane = tid & 31, w = tid >> 5;
    __syncthreads();     // protect warpBuf from previous use
    #pragma unroll
    for (int off = 1; off < 32; off <<= 1) {
        int t = __shfl_down_sync(0xFFFFFFFFu, v, off);
        if (lane + off < 32) v += t;
    }
    if (lane == 0) warpBuf[w] = v;   // whole-warp sum
    __syncthreads();
    if (w == 0) {
        int s = warpBuf[lane];
        #pragma unroll
        for (int off = 1; off < 32; off <<= 1) {
            int t = __shfl_down_sync(0xFFFFFFFFu, s, off);
            if (lane + off < 32) s += t;
        }
        warpBuf[lane] = s;           // inclusive suffix over warp sums
    }
    __syncthreads();
    int later = (w < 31) ? warpBuf[w + 1] : 0;
    return v + later;
}

#define NIT_U   16
#define NIT_I   15
#define CNT_TOTAL 64
// dynamic smem layout: keys[4096] ull (32KB) | selC[4096] int (16KB) |
//                      fill[4096] int (16KB) | grpSuf[1024] int (4KB)  = 69632 B
#define SELECT_SMEM 69632

extern __shared__ char dynsmem[];

__global__ void __launch_bounds__(1024) k_select(const float* __restrict__ pred) {
    int b = blockIdx.x;
    int tid = threadIdx.x;
    int lane = tid & 31;
    const unsigned* u = g_u + b * NPRED;
    ull* keys   = (ull*)dynsmem;                 // 4096 keys
    int* selC   = (int*)(dynsmem + 32768);       // hist -> selected counts
    int* fill   = (int*)(dynsmem + 49152);       // bucket fill counters
    int* grpSuf = (int*)(dynsmem + 65536);       // 1024 group suffix sums
    __shared__ int cnts[CNT_TOTAL];
    __shared__ int warpBuf[32];
    __shared__ int sB, sNeed, sBinCnt, sMode, sG, sMax;
    __shared__ ull sKstar;
    __shared__ int scnt, svalid;

    // zero per-batch side state
    if (tid < NC) g_clsCnt[b * NC + tid] = 0;
    if (tid == 0) { g_ecnt[b] = 0; g_done[b] = 0; scnt = 0; svalid = 0; sMax = 0; }
    if (tid < CNT_TOTAL) cnts[tid] = 0;

    // ---- load all keys into registers (one pass over memory) ----
    unsigned uv[NITEMS];
    #pragma unroll
    for (int k = 0; k < NITEMS; ++k) {
        int i = k * 1024 + tid;
        uv[k] = (i < NPRED) ? u[i] : 0u;   // padding u=0: never matches anything
    }

    // ---- phase 1: 4096-bin histogram of valid keys ----
    #pragma unroll
    for (int h = tid; h < 4096; h += 1024) selC[h] = 0;
    __syncthreads();
    #pragma unroll
    for (int k = 0; k < NITEMS; ++k) {
        unsigned k0 = uv[k];
        if (k0 > U_BASE) {
            int bin = (int)((k0 - U_BASE - 1u) >> 12);
            if (bin > 4095) bin = 4095;
            atomicAdd(&selC[bin], 1);
        }
    }
    __syncthreads();

    // ---- phase 2: suffix-scan over 1024 groups of 4 bins (shfl-based) ----
    {
        int g4 = tid * 4;
        int v = selC[g4] + selC[g4 + 1] + selC[g4 + 2] + selC[g4 + 3];
        int r = blockSuffixScan1024(v, tid, warpBuf);
        grpSuf[tid] = r;
        __syncthreads();
    }
    int totalValid = grpSuf[0];
    if (totalValid >= TOPK) {
        if (grpSuf[tid] >= TOPK && (tid == 1023 || grpSuf[tid + 1] < TOPK)) sG = tid;
        __syncthreads();
        if (tid == 0) {
            int g = sG;
            int c2 = (g < 1023) ? grpSuf[g + 1] : 0;
            int Bst = g * 4, cntGt = c2;
            for (int bb = g * 4 + 3; bb >= g * 4; --bb) {
                if (c2 + selC[bb] >= TOPK) { Bst = bb; cntGt = c2; break; }
                c2 += selC[bb];
            }
            sB = Bst; sNeed = TOPK - cntGt; sBinCnt = selC[Bst]; sMode = 0;
        }
    } else {
        if (tid == 0) { sB = -1; sNeed = TOPK - totalValid; sBinCnt = NPRED - totalValid; sMode = 1; }
    }
    __syncthreads();
    int Bst = sB, need = sNeed, binCnt = sBinCnt, mode = sMode;
    __syncthreads();

    // ---- phase 3: exact threshold key K* ----
    if (binCnt <= TOPK) {
        // gather candidate-bin keys into keys[], tiny bitonic, K* = need-th largest
        if (tid == 0) scnt = 0;
        __syncthreads();
        #pragma unroll
        for (int k = 0; k < NITEMS; ++k) {
            int i = k * 1024 + tid;
            unsigned k0 = uv[k];
            bool m;
            if (mode == 0) {
                int bin = -1;
                if (k0 > U_BASE) {
                    bin = (int)((k0 - U_BASE - 1u) >> 12);
                    if (bin > 4095) bin = 4095;
                }
                m = (bin == Bst);
            } else {
                m = (k0 == U_INVALID) && (i < NPRED);
            }
            if (m) {
                int p = atomicAdd(&scnt, 1);
                if (p < TOPK) keys[p] = ((ull)k0 << 32) | (unsigned)(~i);
            }
        }
        __syncthreads();
        int cnt = scnt;
        int n = 2; while (n < cnt) n <<= 1;
        for (int e = tid; e < n; e += 1024) if (e >= cnt) keys[e] = 0ULL;
        __syncthreads();
        for (int k = 2; k <= n; k <<= 1) {
            for (int j = k >> 1; j >= 1; j >>= 1) {
                for (int x = tid; x < n; x += 1024) {
                    int l = x ^ j;
                    if (l > x) {
                        bool desc = ((x & k) == 0);
                        ull a = keys[x], c = keys[l];
                        if (desc ? (a < c) : (a > c)) { keys[x] = c; keys[l] = a; }
                    }
                }
                __syncthreads();
            }
        }
        if (tid == 0) sKstar = keys[need - 1];
        __syncthreads();
    } else {
        // fallback (never expected): 2-bit search + tie search
        unsigned U = 0u;
        #pragma unroll
        for (int it = 0; it < NIT_U; ++it) {
            int s = 30 - 2 * it;
            unsigned c1t = U + (1u << s);
            int c1 = 0, c2 = 0, c3 = 0;
            #pragma unroll
            for (int k = 0; k < NITEMS; ++k) {
                unsigned k0 = uv[k];
                if (k0 >= c1t) {
                    unsigned w = (k0 - U) >> s;
                    c1++;
                    if (w >= 2) c2++;
                    if (w >= 3) c3++;
                }
            }
            c1 = __reduce_add_sync(0xFFFFFFFFu, c1);
            c2 = __reduce_add_sync(0xFFFFFFFFu, c2);
            c3 = __reduce_add_sync(0xFFFFFFFFu, c3);
            if (lane == 0) {
                atomicAdd(&cnts[it * 3 + 0], c1);
                atomicAdd(&cnts[it * 3 + 1], c2);
                atomicAdd(&cnts[it * 3 + 2], c3);
            }
            __syncthreads();
            int t1 = cnts[it * 3 + 0], t2 = cnts[it * 3 + 1], t3 = cnts[it * 3 + 2];
            unsigned v = (t3 >= TOPK) ? 3u : (t2 >= TOPK) ? 2u : (t1 >= TOPK) ? 1u : 0u;
            U |= v << s;
        }
        unsigned ustar = U;
        {
            int c = 0;
            #pragma unroll
            for (int k = 0; k < NITEMS; ++k) c += (uv[k] > ustar);
            c = __reduce_add_sync(0xFFFFFFFFu, c);
            if (lane == 0) atomicAdd(&cnts[48], c);
            __syncthreads();
        }
        int need2 = TOPK - cnts[48];
        int M = 0;
        #pragma unroll
        for (int it = 0; it < NIT_I; ++it) {
            int bit = 14 - it;
            int candi = M | (1 << bit);
            int c = 0;
            #pragma unroll
            for (int k = 0; k < NITEMS; ++k) {
                int i = k * 1024 + tid;
                if (uv[k] == ustar && i < candi && i < NPRED) c++;
            }
            c = __reduce_add_sync(0xFFFFFFFFu, c);
            if (lane == 0) atomicAdd(&cnts[49 + it], c);
            __syncthreads();
            if (cnts[49 + it] < need2) M = candi;
        }
        if (tid == 0) sKstar = ((ull)ustar << 32) | (unsigned)(~M);
        __syncthreads();
    }
    ull Kstar = sKstar;
    __syncthreads();

    // ---- phase 4: selected-count conversion + bucket-size guard ----
    bool fastOK = false;
    if (mode == 0) {
        #pragma unroll
        for (int h = tid; h < 4096; h += 1024) {
            if (h < Bst) selC[h] = 0;
            else if (h == Bst) selC[h] = need;
        }
        __syncthreads();
        int mymax = 0;
        #pragma unroll
        for (int h = tid; h < 4096; h += 1024) if (selC[h] > mymax) mymax = selC[h];
        mymax = __reduce_max_sync(0xFFFFFFFFu, mymax);
        if (lane == 0) atomicMax(&sMax, mymax);
        __syncthreads();
        fastOK = (sMax <= 64);
    }

    if (fastOK) {
        // ---- phase 5a: suffix-scan of selected counts, scatter to final slots ----
        {
            int g4 = tid * 4;
            int v = selC[g4] + selC[g4 + 1] + selC[g4 + 2] + selC[g4 + 3];
            int r = blockSuffixScan1024(v, tid, warpBuf);
            grpSuf[tid] = r;
        }
        #pragma unroll
        for (int h = tid; h < 4096; h += 1024) fill[h] = 0;
        __syncthreads();
        #pragma unroll
        for (int k = 0; k < NITEMS; ++k) {
            int i = k * 1024 + tid;
            unsigned k0 = uv[k];
            ull key = ((ull)k0 << 32) | (unsigned)(~i);
            if (i < NPRED && key >= Kstar) {
                int bin = (int)((k0 - U_BASE - 1u) >> 12);
                if (bin > 4095) bin = 4095;
                int g = bin >> 2;
                int base = (g < 1023) ? grpSuf[g + 1] : 0;
                for (int b2 = (g << 2) + 3; b2 > bin; --b2) base += selC[b2];
                int slot = base + atomicAdd(&fill[bin], 1);
                keys[slot] = key;
            }
        }
        __syncthreads();
        // ---- per-bucket insertion sort (descending; buckets <= 64) ----
        for (int bin = tid; bin < 4096; bin += 1024) {
            int cnt = selC[bin];
            if (cnt > 1) {
                int g = bin >> 2;
                int base = (g < 1023) ? grpSuf[g + 1] : 0;
                for (int b2 = (g << 2) + 3; b2 > bin; --b2) base += selC[b2];
                for (int a = 1; a < cnt; ++a) {
                    ull kv = keys[base + a];
                    int q = a - 1;
                    while (q >= 0 && keys[base + q] < kv) { keys[base + q + 1] = keys[base + q]; --q; }
                    keys[base + q + 1] = kv;
                }
            }
        }
        __syncthreads();
    } else {
        // ---- phase 5b (fallback): gather + full hybrid bitonic ----
        if (tid == 0) scnt = 0;
        __syncthreads();
        #pragma unroll
        for (int k = 0; k < NITEMS; ++k) {
            int i = k * 1024 + tid;
            ull key = ((ull)uv[k] << 32) | (unsigned)(~i);
            bool m = (i < NPRED) && (key >= Kstar);
            unsigned act = __ballot_sync(0xFFFFFFFFu, m);
            if (m) {
                int leader = __ffs(act) - 1;
                int rank = __popc(act & ((1u << lane) - 1u));
                int base;
                if (lane == leader) base = atomicAdd(&scnt, __popc(act));
                base = __shfl_sync(act, base, leader);
                int pos = base + rank;
                if (pos < TOPK) keys[pos] = key;
            }
        }
        __syncthreads();
        ull v[4];
        #pragma unroll
        for (int e = 0; e < 4; ++e) v[e] = keys[tid * 4 + e];
        for (int k = 2; k <= TOPK; k <<= 1) {
            for (int j = k >> 1; j >= 1; j >>= 1) {
                if (j >= 128) {
                    #pragma unroll
                    for (int e = 0; e < 4; ++e) keys[tid * 4 + e] = v[e];
                    __syncthreads();
                    #pragma unroll
                    for (int e = 0; e < 4; ++e) {
                        int idx = tid * 4 + e;
                        ull pv = keys[idx ^ j];
                        bool d = ((idx & k) == 0);
                        bool lower = ((idx & j) == 0);
                        bool keepmax = (d == lower);
                        ull mx = (v[e] > pv) ? v[e] : pv;
                        ull mn = (v[e] > pv) ? pv : v[e];
                        v[e] = keepmax ? mx : mn;
                    }
                    __syncthreads();
                } else if (j >= 4) {
                    int dl = j >> 2;
                    #pragma unroll
                    for (int e = 0; e < 4; ++e) {
                        ull pv = shfl_xor_u64(v[e], dl);
                        int idx = tid * 4 + e;
                        bool d = ((idx & k) == 0);
                        bool lower = ((tid & dl) == 0);
                        bool keepmax = (d == lower);
                        ull mx = (v[e] > pv) ? v[e] : pv;
                        ull mn = (v[e] > pv) ? pv : v[e];
                        v[e] = keepmax ? mx : mn;
                    }
                } else {
                    #pragma unroll
                    for (int e = 0; e < 4; ++e) {
                        if ((e & j) == 0) {
                            int idx = tid * 4 + e;
                            bool d = ((idx & k) == 0);
                            ull a = v[e], c2 = v[e + j];
                            if (d ? (a < c2) : (a > c2)) { v[e] = c2; v[e + j] = a; }
                        }
                    }
                }
            }
        }
        #pragma unroll
        for (int e = 0; e < 4; ++e) keys[tid * 4 + e] = v[e];
        __syncthreads();
    }

    // ---- emit + fused gather of boxes / classes / areas + class bucketing ----
    int lv = 0;
    #pragma unroll
    for (int e = 0; e < 4; ++e) {
        int rank = tid * 4 + e;
        ull key = keys[rank];
        unsigned k0 = (unsigned)(key >> 32);
        int i = (int)(~(unsigned)(key & 0xFFFFFFFFull));
        int gi = b * TOPK + rank;
        // s exactly recovered from the order key (mapping is invertible)
        float s = (k0 & 0x80000000u) ? __uint_as_float(k0 & 0x7FFFFFFFu) : -1.0f;
        g_selScore[gi] = s;
        lv += (s > 0.0f);
        int ci = g_cls[b * NPRED + i];
        g_selCls[gi] = ci;
        int slot = atomicAdd(&g_clsCnt[b * NC + ci], 1);
        g_clsList[(b * NC + ci) * TOPK + slot] = rank;
        const float* p = pred + ((size_t)b * NPRED + i) * STRIDE;
        float xc = p[0], yc = p[1], w = p[2], h = p[3];
        float hw = __fmul_rn(w, 0.5f), hh = __fmul_rn(h, 0.5f);
        float x1 = __fsub_rn(xc, hw), y1 = __fsub_rn(yc, hh);
        float x2 = __fadd_rn(xc, hw), y2 = __fadd_rn(yc, hh);
        float off = __fmul_rn((float)ci, MAX_WH);
        float ox1 = __fadd_rn(x1, off), oy1 = __fadd_rn(y1, off);
        float ox2 = __fadd_rn(x2, off), oy2 = __fadd_rn(y2, off);
        ((float4*)g_box)[gi] = make_float4(x1, y1, x2, y2);
        ((float4*)g_ob)[gi]  = make_float4(ox1, oy1, ox2, oy2);
        g_area[gi] = __fmul_rn(__fsub_rn(ox2, ox1), __fsub_rn(oy2, oy1));
    }
    lv = __reduce_add_sync(0xFFFFFFFFu, lv);
    if (lane == 0) atomicAdd(&svalid, lv);
    __syncthreads();
    if (tid == 0) g_nvalid[b] = svalid;
}

// -------- kernel 3: per-class IoU -> pairs, then LAST block per batch suppresses -----
__device__ __forceinline__ bool iou_exceeds(float ax1, float ay1, float ax2, float ay2,
                                            float aA,
                                            float bx1, float by1, float bx2, float by2,
                                            float aB) {
    float ltx = fmaxf(ax1, bx1);
    float lty = fmaxf(ay1, by1);
    float rbx = fminf(ax2, bx2);
    float rby = fminf(ay2, by2);
    float wv = fmaxf(__fsub_rn(rbx, ltx), 0.0f);
    float hv = fmaxf(__fsub_rn(rby, lty), 0.0f);
    float inter = __fmul_rn(wv, hv);
    if (inter <= 0.0f) return false;
    float denom = __fadd_rn(__fsub_rn(__fadd_rn(aA, aB), inter), 1e-7f);
    return __fdiv_rn(inter, denom) > IOU_THRES;
}

struct MaskShm {
    float sx1[MCACHE], sy1[MCACHE], sx2[MCACHE], sy2[MCACHE], sar[MCACHE];
    int   srk[MCACHE];
};
struct SupShm {
    unsigned sedge[ECAP];
    ull remA[NWORDS], remB[NWORDS], keepw[NWORDS];
    int prefix[NWORDS];
};

__global__ void __launch_bounds__(256) k_mask(float* __restrict__ out) {
    __shared__ union { MaskShm m; SupShm s; } shm;
    __shared__ int sLast, schanged;
    int c = blockIdx.x;     // class
    int b = blockIdx.y;     // batch
    int tid = threadIdx.x;
    int n = g_clsCnt[b * NC + c];

    // ---- phase A: pair generation for this class ----
    if (n >= 2) {
        const int* gl = g_clsList + (b * NC + c) * TOPK;
        bool cached = (n <= MCACHE);
        if (cached) {
            for (int s = tid; s < n; s += 256) {
                int r = gl[s];
                float4 B = ((const float4*)g_ob)[b * TOPK + r];
                shm.m.sx1[s] = B.x; shm.m.sy1[s] = B.y;
                shm.m.sx2[s] = B.z; shm.m.sy2[s] = B.w;
                shm.m.sar[s] = g_area[b * TOPK + r];
                shm.m.srk[s] = r;
            }
            __syncthreads();
        }
        long long total = (long long)n * (n - 1) / 2;
        long long per = (total + 255) >> 8;
        long long p0 = (long long)tid * per;
        long long p1 = p0 + per; if (p1 > total) p1 = total;
        if (p0 < p1) {
            // find starting row a for p0 (one sqrt + exact fixup), then step incrementally
            float fn = (float)n;
            int a = (int)(fn - 0.5f - sqrtf(fmaxf((fn - 0.5f) * (fn - 0.5f) - 2.0f * (float)p0, 0.0f)));
            if (a < 0) a = 0; if (a > n - 2) a = n - 2;
            while ((long long)(a + 1) * n - (long long)(a + 1) * (a + 2) / 2 <= p0) a++;
            while ((long long)a * n - (long long)a * (a + 1) / 2 > p0) a--;
            long long fa = (long long)a * n - (long long)a * (a + 1) / 2;
            int bq = (int)(p0 - fa) + a + 1;
            for (long long p = p0; p < p1; ++p) {
                bool hit; int r1, r2;
                if (cached) {
                    r1 = shm.m.srk[a]; r2 = shm.m.srk[bq];
                    hit = iou_exceeds(shm.m.sx1[a], shm.m.sy1[a], shm.m.sx2[a], shm.m.sy2[a], shm.m.sar[a],
                                      shm.m.sx1[bq], shm.m.sy1[bq], shm.m.sx2[bq], shm.m.sy2[bq], shm.m.sar[bq]);
                } else {
                    r1 = gl[a]; r2 = gl[bq];
                    int gi = b * TOPK + r1, gj = b * TOPK + r2;
                    float4 A = ((const float4*)g_ob)[gi];
                    float4 B = ((const float4*)g_ob)[gj];
                    hit = iou_exceeds(A.x, A.y, A.z, A.w, g_area[gi],
                                      B.x, B.y, B.z, B.w, g_area[gj]);
                }
                if (hit) {
                    int i = min(r1, r2), j = max(r1, r2);
                    int e = atomicAdd(&g_ecnt[b], 1);
                    if (e < ECAP) g_epair[b * ECAP + e] = ((unsigned)i << 12) | (unsigned)j;
                }
                if (++bq >= n) { ++a; bq = a + 1; }
            }
        }
    }

    // ---- phase B: completion counter; last block of batch b runs suppression ----
    __threadfence();
    __syncthreads();
    if (tid == 0) sLast = (atomicAdd(&g_done[b], 1) == NC - 1);
    __syncthreads();
    if (!sLast) return;
    __threadfence();   // acquire: other blocks' pair writes are now visible

    int nv = g_nvalid[b];
    int cnt = g_ecnt[b];
    if (tid < NWORDS) shm.s.remA[tid] = 0ULL;

    if (cnt <= ECAP) {
        // greedy NMS = unique fixpoint of alive(j) = valid(j) && !exists edge(i,j) alive(i)
        for (int e = tid; e < cnt; e += 256) shm.s.sedge[e] = g_epair[b * ECAP + e];
        __syncthreads();
        for (int round = 0; round <= cnt; ++round) {
            if (tid < NWORDS) shm.s.remB[tid] = 0ULL;
            if (tid == 0) schanged = 0;
            __syncthreads();
            for (int e = tid; e < cnt; e += 256) {
                unsigned k = shm.s.sedge[e];
                int i = (int)(k >> 12);
                if (i < nv && !((shm.s.remA[i >> 6] >> (i & 63)) & 1ULL)) {
                    int j = (int)(k & 4095u);
                    atomicOr(&shm.s.remB[j >> 6], 1ULL << (j & 63));
                }
            }
            __syncthreads();
            if (tid < NWORDS && shm.s.remB[tid] != shm.s.remA[tid]) schanged = 1;  // benign race
            __syncthreads();
            if (!schanged) break;
            if (tid < NWORDS) shm.s.remA[tid] = shm.s.remB[tid];
            __syncthreads();
        }
    } else {
        // fallback (never expected): exact serial greedy from class lists
        if (tid == 0) {
            for (int i = 0; i < nv; ++i) {
                if ((shm.s.remA[i >> 6] >> (i & 63)) & 1ULL) continue;
                int cc = g_selCls[b * TOPK + i];
                int nn = g_clsCnt[b * NC + cc];
                const int* gl2 = g_clsList + (b * NC + cc) * TOPK;
                float4 A = ((const float4*)g_ob)[b * TOPK + i];
                float aA = g_area[b * TOPK + i];
                for (int s = 0; s < nn; ++s) {
                    int j = gl2[s];
                    if (j <= i) continue;
                    if ((shm.s.remA[j >> 6] >> (j & 63)) & 1ULL) continue;
                    float4 B = ((const float4*)g_ob)[b * TOPK + j];
                    if (iou_exceeds(A.x, A.y, A.z, A.w, aA,
                                    B.x, B.y, B.z, B.w, g_area[b * TOPK + j]))
                        shm.s.remA[j >> 6] |= (1ULL << (j & 63));
                }
            }
        }
        __syncthreads();
    }

    if (tid < NWORDS) {
        int lim = nv - tid * 64; if (lim > 64) lim = 64; if (lim < 0) lim = 0;
        ull valid = (lim >= 64) ? ~0ULL : ((lim <= 0) ? 0ULL : ((1ULL << lim) - 1ULL));
        shm.s.keepw[tid] = valid & ~shm.s.remA[tid];
    }
    __syncthreads();

    // ---- fused output compaction ----
    if (tid == 0) {
        int s = 0;
        for (int w = 0; w < NWORDS; ++w) { shm.s.prefix[w] = s; s += __popcll(shm.s.keepw[w]); }
    }
    float* o = out + (size_t)b * MAXDET * 6;
    for (int z = tid; z < MAXDET * 6; z += 256) o[z] = 0.0f;
    __syncthreads();
    for (int i = tid; i < TOPK; i += 256) {
        int w = i >> 6, bt = i & 63;
        if ((shm.s.keepw[w] >> bt) & 1ULL) {
            int rank = shm.s.prefix[w] + __popcll(shm.s.keepw[w] & ((1ULL << bt) - 1ULL));
            if (rank < MAXDET) {
                int gi = b * TOPK + i;
                float* r = o + rank * 6;
                float4 bx = ((const float4*)g_box)[gi];
                r[0] = bx.x; r[1] = bx.y; r[2] = bx.z; r[3] = bx.w;
                r[4] = g_selScore[gi];
                r[5] = (float)g_selCls[gi];
            }
        }
    }
}

// ---------------- launch ---------------------------------------------------------------
extern "C" void kernel_launch(void* const* d_in, const int* in_sizes, int n_in,
                              void* d_out, int out_size) {
    const float* pred = (const float*)d_in[0];
    float* out = (float*)d_out;

    // opt-in to >48KB dynamic shared (attribute set, not an allocation; capture-safe)
    cudaFuncSetAttribute(k_select, cudaFuncAttributeMaxDynamicSharedMemorySize, SELECT_SMEM);

    // 1) conf / argmax / order key : 24 rows per block, 2 rows per warp (interleaved)
    {
        int groups = (BATCH * NPRED) / 24;   // 403200/24 = 16800 exactly
        k_prep<<<groups, 384>>>((const float4*)pred);
    }
    // 2) exact top-4096 per batch (histogram threshold + bucket rank) + fused gather
    k_select<<<BATCH, 1024, SELECT_SMEM>>>(pred);
    // 3) per-class pairwise IoU -> pairs; last block per batch: suppression + output
    {
        dim3 g(NC, BATCH);
        k_mask<<<g, 256>>>(out);
    }
}